// round 16
// baseline (speedup 1.0000x reference)
#include <cuda_runtime.h>
#include <cstdint>

#define TP 94
#define NN 128
#define HH 32

__device__ float g_h[TP * NN * HH];

#define C4(v, u) ((u) == 0 ? (v).x : (u) == 1 ? (v).y : (u) == 2 ? (v).z : (v).w)

// f32x2 helpers: load 16B of smem directly as two 64-bit packed f32x2 regs.
#define LDS_V2U64(a, b, addr) \
    asm volatile("ld.shared.v2.u64 {%0, %1}, [%2];" \
                 : "=l"(a), "=l"(b) : "r"(addr))
#define ADDF2(out, x, y) \
    asm("add.rn.f32x2 %0, %1, %2;" : "=l"(out) : "l"(x), "l"(y))
#define UNPACKF2(lo, hi, in) \
    asm("mov.b64 {%0, %1}, %2;" : "=f"(lo), "=f"(hi) : "l"(in))
#define PACKF2(out, lo, hi) \
    asm("mov.b64 %0, {%1, %2};" : "=l"(out) : "f"(lo), "f"(hi))

// ---------------------------------------------------------------------------
// Kernel 1: conv stack (R9-proven, unchanged). One block per n, 512 threads,
// weights repacked [ic][k][oc], broadcast LDS.128, float4 h rows.
// ---------------------------------------------------------------------------
__global__ void __launch_bounds__(512) conv_kernel(
    const float* __restrict__ x,
    const float* __restrict__ w1, const float* __restrict__ b1,
    const float* __restrict__ w2, const float* __restrict__ b2,
    const float* __restrict__ w3, const float* __restrict__ b3)
{
    __shared__ __align__(16) float x_s[400];
    __shared__ __align__(16) float w1p[192];
    __shared__ __align__(16) float b1_s[16];
    __shared__ __align__(16) float w2p[1536];
    __shared__ __align__(16) float b2_s[32];
    __shared__ __align__(16) float w3p[3072];
    __shared__ __align__(16) float b3_s[32];
    __shared__ __align__(16) float h1_s[98 * 20];
    __shared__ __align__(16) float h2_s[96 * 36];

    const int n = blockIdx.x;
    const int tid = threadIdx.x;
    const int t = tid & 127;
    const int q = tid >> 7;          // 0..3

    for (int idx = tid; idx < 400; idx += 512) x_s[idx] = x[n * 400 + idx];
    for (int idx = tid; idx < 192; idx += 512) {
        int oc = idx / 12, i = (idx % 12) / 3, k = idx % 3;
        w1p[(i * 3 + k) * 16 + oc] = w1[idx];
    }
    for (int idx = tid; idx < 1536; idx += 512) {
        int oc = idx / 48, ic = (idx % 48) / 3, k = idx % 3;
        w2p[ic * 96 + k * 32 + oc] = w2[idx];
    }
    for (int idx = tid; idx < 3072; idx += 512) {
        int oc = idx / 96, ic = (idx % 96) / 3, k = idx % 3;
        w3p[ic * 96 + k * 32 + oc] = w3[idx];
    }
    if (tid < 16) b1_s[tid] = b1[tid];
    if (tid < 32) { b2_s[tid] = b2[tid]; b3_s[tid] = b3[tid]; }
    __syncthreads();

    if (t < 98) {
        float4 xa = *(const float4*)&x_s[(t + 0) * 4];
        float4 xb = *(const float4*)&x_s[(t + 1) * 4];
        float4 xc = *(const float4*)&x_s[(t + 2) * 4];
        const int oc0 = q * 4;
        float4 acc = *(const float4*)&b1_s[oc0];
        #pragma unroll
        for (int i = 0; i < 4; i++) {
            #pragma unroll
            for (int k = 0; k < 3; k++) {
                float xv = (k == 0) ? C4(xa, i) : (k == 1) ? C4(xb, i) : C4(xc, i);
                float4 wv = *(const float4*)&w1p[(i * 3 + k) * 16 + oc0];
                acc.x += xv * wv.x; acc.y += xv * wv.y;
                acc.z += xv * wv.z; acc.w += xv * wv.w;
            }
        }
        acc.x = fmaxf(acc.x, 0.f); acc.y = fmaxf(acc.y, 0.f);
        acc.z = fmaxf(acc.z, 0.f); acc.w = fmaxf(acc.w, 0.f);
        *(float4*)&h1_s[t * 20 + oc0] = acc;
    }
    __syncthreads();

    if (t < 96) {
        const int oc0 = q * 8;
        float acc[8];
        #pragma unroll
        for (int o = 0; o < 8; o++) acc[o] = b2_s[oc0 + o];
        #pragma unroll
        for (int ic4 = 0; ic4 < 4; ic4++) {
            float4 ha = *(const float4*)&h1_s[(t + 0) * 20 + ic4 * 4];
            float4 hb = *(const float4*)&h1_s[(t + 1) * 20 + ic4 * 4];
            float4 hc = *(const float4*)&h1_s[(t + 2) * 20 + ic4 * 4];
            #pragma unroll
            for (int u = 0; u < 4; u++) {
                int ic = ic4 * 4 + u;
                #pragma unroll
                for (int k = 0; k < 3; k++) {
                    float hk = (k == 0) ? C4(ha, u) : (k == 1) ? C4(hb, u) : C4(hc, u);
                    float4 wa = *(const float4*)&w2p[ic * 96 + k * 32 + oc0];
                    float4 wb = *(const float4*)&w2p[ic * 96 + k * 32 + oc0 + 4];
                    acc[0] += hk * wa.x; acc[1] += hk * wa.y;
                    acc[2] += hk * wa.z; acc[3] += hk * wa.w;
                    acc[4] += hk * wb.x; acc[5] += hk * wb.y;
                    acc[6] += hk * wb.z; acc[7] += hk * wb.w;
                }
            }
        }
        float4 oa = make_float4(fmaxf(acc[0],0.f), fmaxf(acc[1],0.f),
                                fmaxf(acc[2],0.f), fmaxf(acc[3],0.f));
        float4 ob = make_float4(fmaxf(acc[4],0.f), fmaxf(acc[5],0.f),
                                fmaxf(acc[6],0.f), fmaxf(acc[7],0.f));
        *(float4*)&h2_s[t * 36 + oc0] = oa;
        *(float4*)&h2_s[t * 36 + oc0 + 4] = ob;
    }
    __syncthreads();

    if (t < 94) {
        const int oc0 = q * 8;
        float acc[8];
        #pragma unroll
        for (int o = 0; o < 8; o++) acc[o] = b3_s[oc0 + o];
        #pragma unroll
        for (int ic4 = 0; ic4 < 8; ic4++) {
            float4 ha = *(const float4*)&h2_s[(t + 0) * 36 + ic4 * 4];
            float4 hb = *(const float4*)&h2_s[(t + 1) * 36 + ic4 * 4];
            float4 hc = *(const float4*)&h2_s[(t + 2) * 36 + ic4 * 4];
            #pragma unroll
            for (int u = 0; u < 4; u++) {
                int ic = ic4 * 4 + u;
                #pragma unroll
                for (int k = 0; k < 3; k++) {
                    float hk = (k == 0) ? C4(ha, u) : (k == 1) ? C4(hb, u) : C4(hc, u);
                    float4 wa = *(const float4*)&w3p[ic * 96 + k * 32 + oc0];
                    float4 wb = *(const float4*)&w3p[ic * 96 + k * 32 + oc0 + 4];
                    acc[0] += hk * wa.x; acc[1] += hk * wa.y;
                    acc[2] += hk * wa.z; acc[3] += hk * wa.w;
                    acc[4] += hk * wb.x; acc[5] += hk * wb.y;
                    acc[6] += hk * wb.z; acc[7] += hk * wb.w;
                }
            }
        }
        float4 oa = make_float4(fmaxf(acc[0],0.f), fmaxf(acc[1],0.f),
                                fmaxf(acc[2],0.f), fmaxf(acc[3],0.f));
        float4 ob = make_float4(fmaxf(acc[4],0.f), fmaxf(acc[5],0.f),
                                fmaxf(acc[6],0.f), fmaxf(acc[7],0.f));
        *(float4*)&g_h[(t * NN + n) * HH + oc0] = oa;
        *(float4*)&g_h[(t * NN + n) * HH + oc0 + 4] = ob;
    }
}

// ---------------------------------------------------------------------------
// Kernel 2: R9 structure exactly; ONE change: P2 inner loop uses
// ld.shared.v2.u64 + add.rn.f32x2 for the (v + c) adds (no pack side).
// ---------------------------------------------------------------------------
__global__ void __launch_bounds__(1024) swarm_kernel(
    const float* __restrict__ x,
    const float* __restrict__ We, const float* __restrict__ be,
    const float* __restrict__ Wa, const float* __restrict__ ba,
    const float* __restrict__ Wu, const float* __restrict__ bu,
    const float* __restrict__ Wd, const float* __restrict__ bd,
    float* __restrict__ out)
{
    extern __shared__ float s[];
    float* h_s  = s;            // 128*36 = 4608
    float* ejT  = s + 4608;     // 32*132 = 4224
    float* ci_s = s + 8832;     // 128*32 = 4096
    float* agA  = s + 12928;    // 128*36 = 4608
    float* agB  = s + 17536;    // 128*36 = 4608
    float* upd  = s + 22144;    // 128*36 = 4608
    float* Wep  = s + 26752;    // 2048 (packed [c][d][{wj,wi}])
    float* be_s = s + 28800;    // 32
    float* Wa_s = s + 28832;    // 1024
    float* ba_s = s + 29856;    // 32
    float* Wup  = s + 29888;    // 2048 (packed [c][d][{wh,wa}])
    float* bu_s = s + 31936;    // 32
    float* Wd_s = s + 31968;    // 128
    float* bd_s = s + 32096;    // 4
    // total 32100 floats = 128400 B

    const int t = blockIdx.x;
    const int tid = threadIdx.x;
    const int d = tid & 31;
    const int g = tid >> 5;      // 0..31

    {
        int idx = tid * 4;
        int i = idx >> 5, c = idx & 31;
        float4 v = *(const float4*)&g_h[t * 4096 + idx];
        *(float4*)&h_s[i * 36 + c] = v;
    }
    for (int idx = tid; idx < 2048; idx += 1024) {
        float v = We[idx];
        int half = idx >> 10;
        int c = (idx >> 5) & 31;
        int dd = idx & 31;
        Wep[c * 64 + 2 * dd + half] = v;
    }
    for (int idx = tid; idx < 2048; idx += 1024) {
        float v = Wu[idx];
        int half = idx >> 10;
        int c = (idx >> 5) & 31;
        int dd = idx & 31;
        Wup[c * 64 + 2 * dd + half] = v;
    }
    for (int idx = tid; idx < 1024; idx += 1024) Wa_s[idx] = Wa[idx];
    if (tid < 32) { be_s[tid] = be[tid]; ba_s[tid] = ba[tid]; bu_s[tid] = bu[tid]; }
    else if (tid >= 64 && tid < 192) Wd_s[tid - 64] = Wd[tid - 64];
    else if (tid >= 192 && tid < 196) bd_s[tid - 192] = bd[tid - 192];
    __syncthreads();

    // P1: ejT[d][j] and ci[j][d] = ei + be.
    {
        float aej[4], aei[4];
        float bev = be_s[d];
        #pragma unroll
        for (int ii = 0; ii < 4; ii++) { aej[ii] = 0.f; aei[ii] = bev; }
        #pragma unroll
        for (int c4 = 0; c4 < 8; c4++) {
            float2 w0 = *(const float2*)&Wep[(4 * c4 + 0) * 64 + 2 * d];
            float2 w1v = *(const float2*)&Wep[(4 * c4 + 1) * 64 + 2 * d];
            float2 w2v = *(const float2*)&Wep[(4 * c4 + 2) * 64 + 2 * d];
            float2 w3v = *(const float2*)&Wep[(4 * c4 + 3) * 64 + 2 * d];
            #pragma unroll
            for (int ii = 0; ii < 4; ii++) {
                float4 hv = *(const float4*)&h_s[(g + 32 * ii) * 36 + 4 * c4];
                aej[ii] += hv.x * w0.x;  aei[ii] += hv.x * w0.y;
                aej[ii] += hv.y * w1v.x; aei[ii] += hv.y * w1v.y;
                aej[ii] += hv.z * w2v.x; aei[ii] += hv.z * w2v.y;
                aej[ii] += hv.w * w3v.x; aei[ii] += hv.w * w3v.y;
            }
        }
        #pragma unroll
        for (int ii = 0; ii < 4; ii++) {
            int j = g + 32 * ii;
            ejT[d * 132 + j] = aej[ii];
            ci_s[j * 32 + d] = aei[ii];
        }
    }
    __syncthreads();

    // P2: agg0[i][d] = 0.5*(S_d + 128*c_i + Sum_j |ej_j + c_i|) - relu(ej_i+c_i)
    //     f32x2 adds; row loaded straight into packed 64-bit regs.
    {
        float acc[4], cc[4];
        uint64_t c2[4];
        #pragma unroll
        for (int ii = 0; ii < 4; ii++) {
            cc[ii] = ci_s[(g + 32 * ii) * 32 + d];
            PACKF2(c2[ii], cc[ii], cc[ii]);
            acc[ii] = 0.f;
        }
        uint64_t S2;
        { float z = 0.f; PACKF2(S2, z, z); }

        // smem address of this thread's ejT row (generic->shared cvt)
        uint32_t rowaddr;
        {
            uint64_t gaddr = (uint64_t)&ejT[d * 132];
            asm("{ .reg .u64 tmp; cvta.to.shared.u64 tmp, %1; cvt.u32.u64 %0, tmp; }"
                : "=r"(rowaddr) : "l"(gaddr));
        }
        #pragma unroll 8
        for (int j4 = 0; j4 < 32; j4++) {
            uint64_t v01, v23;
            LDS_V2U64(v01, v23, rowaddr + j4 * 16);
            ADDF2(S2, S2, v01);
            ADDF2(S2, S2, v23);
            #pragma unroll
            for (int ii = 0; ii < 4; ii++) {
                uint64_t t01, t23;
                ADDF2(t01, v01, c2[ii]);
                ADDF2(t23, v23, c2[ii]);
                float a0, a1, b0, b1;
                UNPACKF2(a0, a1, t01);
                UNPACKF2(b0, b1, t23);
                acc[ii] += fabsf(a0);
                acc[ii] += fabsf(a1);
                acc[ii] += fabsf(b0);
                acc[ii] += fabsf(b1);
            }
        }
        float Sl, Sh;
        UNPACKF2(Sl, Sh, S2);
        float S = Sl + Sh;
        #pragma unroll
        for (int ii = 0; ii < 4; ii++) {
            int i = g + 32 * ii;
            float diag = fmaxf(ejT[d * 132 + i] + cc[ii], 0.f);
            agA[i * 36 + d] = 0.5f * (S + 128.f * cc[ii] + acc[ii]) - diag;
        }
    }
    __syncthreads();

    // P3: agg = relu(agg0 @ Wa + ba)
    {
        float acc[4];
        float bav = ba_s[d];
        #pragma unroll
        for (int ii = 0; ii < 4; ii++) acc[ii] = bav;
        #pragma unroll
        for (int c4 = 0; c4 < 8; c4++) {
            float wq0 = Wa_s[(4 * c4 + 0) * 32 + d];
            float wq1 = Wa_s[(4 * c4 + 1) * 32 + d];
            float wq2 = Wa_s[(4 * c4 + 2) * 32 + d];
            float wq3 = Wa_s[(4 * c4 + 3) * 32 + d];
            #pragma unroll
            for (int ii = 0; ii < 4; ii++) {
                float4 av = *(const float4*)&agA[(g + 32 * ii) * 36 + 4 * c4];
                acc[ii] += av.x * wq0 + av.y * wq1 + av.z * wq2 + av.w * wq3;
            }
        }
        #pragma unroll
        for (int ii = 0; ii < 4; ii++)
            agB[(g + 32 * ii) * 36 + d] = fmaxf(acc[ii], 0.f);
    }
    __syncthreads();

    // P4: upd = relu(h @ Wu[:H] + agg @ Wu[H:] + bu)
    {
        float acc[4];
        float buv = bu_s[d];
        #pragma unroll
        for (int ii = 0; ii < 4; ii++) acc[ii] = buv;
        #pragma unroll
        for (int c4 = 0; c4 < 8; c4++) {
            float2 w0 = *(const float2*)&Wup[(4 * c4 + 0) * 64 + 2 * d];
            float2 w1v = *(const float2*)&Wup[(4 * c4 + 1) * 64 + 2 * d];
            float2 w2v = *(const float2*)&Wup[(4 * c4 + 2) * 64 + 2 * d];
            float2 w3v = *(const float2*)&Wup[(4 * c4 + 3) * 64 + 2 * d];
            #pragma unroll
            for (int ii = 0; ii < 4; ii++) {
                int r = (g + 32 * ii) * 36 + 4 * c4;
                float4 hv = *(const float4*)&h_s[r];
                float4 av = *(const float4*)&agB[r];
                acc[ii] += hv.x * w0.x  + av.x * w0.y;
                acc[ii] += hv.y * w1v.x + av.y * w1v.y;
                acc[ii] += hv.z * w2v.x + av.z * w2v.y;
                acc[ii] += hv.w * w3v.x + av.w * w3v.y;
            }
        }
        #pragma unroll
        for (int ii = 0; ii < 4; ii++)
            upd[(g + 32 * ii) * 36 + d] = fmaxf(acc[ii], 0.f);
    }
    __syncthreads();

    // P5: dec = upd @ Wd + bd;  out = x[:, 6+t] + dec  (first 512 threads)
    if (tid < 512) {
        int i = tid >> 2, dd = tid & 3;
        float acc = bd_s[dd];
        #pragma unroll
        for (int dc = 0; dc < 32; dc++)
            acc += upd[i * 36 + dc] * Wd_s[dc * 4 + dd];
        out[(i * TP + t) * 4 + dd] = x[(i * 100 + 6 + t) * 4 + dd] + acc;
    }
}

// ---------------------------------------------------------------------------
extern "C" void kernel_launch(void* const* d_in, const int* in_sizes, int n_in,
                              void* d_out, int out_size)
{
    const float* x  = (const float*)d_in[0];
    const float* w1 = (const float*)d_in[1];
    const float* b1 = (const float*)d_in[2];
    const float* w2 = (const float*)d_in[3];
    const float* b2 = (const float*)d_in[4];
    const float* w3 = (const float*)d_in[5];
    const float* b3 = (const float*)d_in[6];
    const float* We = (const float*)d_in[7];
    const float* be = (const float*)d_in[8];
    const float* Wa = (const float*)d_in[9];
    const float* ba = (const float*)d_in[10];
    const float* Wu = (const float*)d_in[11];
    const float* bu = (const float*)d_in[12];
    const float* Wd = (const float*)d_in[13];
    const float* bd = (const float*)d_in[14];
    float* out = (float*)d_out;

    cudaFuncSetAttribute(swarm_kernel,
                         cudaFuncAttributeMaxDynamicSharedMemorySize, 32100 * 4);

    conv_kernel<<<128, 512>>>(x, w1, b1, w2, b2, w3, b3);
    swarm_kernel<<<94, 1024, 32100 * 4>>>(x, We, be, Wa, ba, Wu, bu, Wd, bd, out);
}

// round 17
// speedup vs baseline: 1.0703x; 1.0703x over previous
#include <cuda_runtime.h>

#define TP 94
#define NN 128
#define HH 32

__device__ float g_h[TP * NN * HH];

#define C4(v, u) ((u) == 0 ? (v).x : (u) == 1 ? (v).y : (u) == 2 ? (v).z : (v).w)

// ---------------------------------------------------------------------------
// Kernel 1: conv stack (R9-proven, unchanged). One block per n, 512 threads,
// weights repacked [ic][k][oc], broadcast LDS.128, float4 h rows.
// ---------------------------------------------------------------------------
__global__ void __launch_bounds__(512) conv_kernel(
    const float* __restrict__ x,
    const float* __restrict__ w1, const float* __restrict__ b1,
    const float* __restrict__ w2, const float* __restrict__ b2,
    const float* __restrict__ w3, const float* __restrict__ b3)
{
    __shared__ __align__(16) float x_s[400];
    __shared__ __align__(16) float w1p[192];
    __shared__ __align__(16) float b1_s[16];
    __shared__ __align__(16) float w2p[1536];
    __shared__ __align__(16) float b2_s[32];
    __shared__ __align__(16) float w3p[3072];
    __shared__ __align__(16) float b3_s[32];
    __shared__ __align__(16) float h1_s[98 * 20];
    __shared__ __align__(16) float h2_s[96 * 36];

    const int n = blockIdx.x;
    const int tid = threadIdx.x;
    const int t = tid & 127;
    const int q = tid >> 7;          // 0..3

    for (int idx = tid; idx < 400; idx += 512) x_s[idx] = x[n * 400 + idx];
    for (int idx = tid; idx < 192; idx += 512) {
        int oc = idx / 12, i = (idx % 12) / 3, k = idx % 3;
        w1p[(i * 3 + k) * 16 + oc] = w1[idx];
    }
    for (int idx = tid; idx < 1536; idx += 512) {
        int oc = idx / 48, ic = (idx % 48) / 3, k = idx % 3;
        w2p[ic * 96 + k * 32 + oc] = w2[idx];
    }
    for (int idx = tid; idx < 3072; idx += 512) {
        int oc = idx / 96, ic = (idx % 96) / 3, k = idx % 3;
        w3p[ic * 96 + k * 32 + oc] = w3[idx];
    }
    if (tid < 16) b1_s[tid] = b1[tid];
    if (tid < 32) { b2_s[tid] = b2[tid]; b3_s[tid] = b3[tid]; }
    __syncthreads();

    if (t < 98) {
        float4 xa = *(const float4*)&x_s[(t + 0) * 4];
        float4 xb = *(const float4*)&x_s[(t + 1) * 4];
        float4 xc = *(const float4*)&x_s[(t + 2) * 4];
        const int oc0 = q * 4;
        float4 acc = *(const float4*)&b1_s[oc0];
        #pragma unroll
        for (int i = 0; i < 4; i++) {
            #pragma unroll
            for (int k = 0; k < 3; k++) {
                float xv = (k == 0) ? C4(xa, i) : (k == 1) ? C4(xb, i) : C4(xc, i);
                float4 wv = *(const float4*)&w1p[(i * 3 + k) * 16 + oc0];
                acc.x += xv * wv.x; acc.y += xv * wv.y;
                acc.z += xv * wv.z; acc.w += xv * wv.w;
            }
        }
        acc.x = fmaxf(acc.x, 0.f); acc.y = fmaxf(acc.y, 0.f);
        acc.z = fmaxf(acc.z, 0.f); acc.w = fmaxf(acc.w, 0.f);
        *(float4*)&h1_s[t * 20 + oc0] = acc;
    }
    __syncthreads();

    if (t < 96) {
        const int oc0 = q * 8;
        float acc[8];
        #pragma unroll
        for (int o = 0; o < 8; o++) acc[o] = b2_s[oc0 + o];
        #pragma unroll
        for (int ic4 = 0; ic4 < 4; ic4++) {
            float4 ha = *(const float4*)&h1_s[(t + 0) * 20 + ic4 * 4];
            float4 hb = *(const float4*)&h1_s[(t + 1) * 20 + ic4 * 4];
            float4 hc = *(const float4*)&h1_s[(t + 2) * 20 + ic4 * 4];
            #pragma unroll
            for (int u = 0; u < 4; u++) {
                int ic = ic4 * 4 + u;
                #pragma unroll
                for (int k = 0; k < 3; k++) {
                    float hk = (k == 0) ? C4(ha, u) : (k == 1) ? C4(hb, u) : C4(hc, u);
                    float4 wa = *(const float4*)&w2p[ic * 96 + k * 32 + oc0];
                    float4 wb = *(const float4*)&w2p[ic * 96 + k * 32 + oc0 + 4];
                    acc[0] += hk * wa.x; acc[1] += hk * wa.y;
                    acc[2] += hk * wa.z; acc[3] += hk * wa.w;
                    acc[4] += hk * wb.x; acc[5] += hk * wb.y;
                    acc[6] += hk * wb.z; acc[7] += hk * wb.w;
                }
            }
        }
        float4 oa = make_float4(fmaxf(acc[0],0.f), fmaxf(acc[1],0.f),
                                fmaxf(acc[2],0.f), fmaxf(acc[3],0.f));
        float4 ob = make_float4(fmaxf(acc[4],0.f), fmaxf(acc[5],0.f),
                                fmaxf(acc[6],0.f), fmaxf(acc[7],0.f));
        *(float4*)&h2_s[t * 36 + oc0] = oa;
        *(float4*)&h2_s[t * 36 + oc0 + 4] = ob;
    }
    __syncthreads();

    if (t < 94) {
        const int oc0 = q * 8;
        float acc[8];
        #pragma unroll
        for (int o = 0; o < 8; o++) acc[o] = b3_s[oc0 + o];
        #pragma unroll
        for (int ic4 = 0; ic4 < 8; ic4++) {
            float4 ha = *(const float4*)&h2_s[(t + 0) * 36 + ic4 * 4];
            float4 hb = *(const float4*)&h2_s[(t + 1) * 36 + ic4 * 4];
            float4 hc = *(const float4*)&h2_s[(t + 2) * 36 + ic4 * 4];
            #pragma unroll
            for (int u = 0; u < 4; u++) {
                int ic = ic4 * 4 + u;
                #pragma unroll
                for (int k = 0; k < 3; k++) {
                    float hk = (k == 0) ? C4(ha, u) : (k == 1) ? C4(hb, u) : C4(hc, u);
                    float4 wa = *(const float4*)&w3p[ic * 96 + k * 32 + oc0];
                    float4 wb = *(const float4*)&w3p[ic * 96 + k * 32 + oc0 + 4];
                    acc[0] += hk * wa.x; acc[1] += hk * wa.y;
                    acc[2] += hk * wa.z; acc[3] += hk * wa.w;
                    acc[4] += hk * wb.x; acc[5] += hk * wb.y;
                    acc[6] += hk * wb.z; acc[7] += hk * wb.w;
                }
            }
        }
        float4 oa = make_float4(fmaxf(acc[0],0.f), fmaxf(acc[1],0.f),
                                fmaxf(acc[2],0.f), fmaxf(acc[3],0.f));
        float4 ob = make_float4(fmaxf(acc[4],0.f), fmaxf(acc[5],0.f),
                                fmaxf(acc[6],0.f), fmaxf(acc[7],0.f));
        *(float4*)&g_h[(t * NN + n) * HH + oc0] = oa;
        *(float4*)&g_h[(t * NN + n) * HH + oc0 + 4] = ob;
    }
}

// ---------------------------------------------------------------------------
// Kernel 2: R9 structure; ONE change vs R9: P1's aej/aei stay in registers
// across the barrier, so P2 needs no ci_s loads and no diag ejT loads
// (thread (g,d) produced exactly the values it consumes).
// ---------------------------------------------------------------------------
__global__ void __launch_bounds__(1024) swarm_kernel(
    const float* __restrict__ x,
    const float* __restrict__ We, const float* __restrict__ be,
    const float* __restrict__ Wa, const float* __restrict__ ba,
    const float* __restrict__ Wu, const float* __restrict__ bu,
    const float* __restrict__ Wd, const float* __restrict__ bd,
    float* __restrict__ out)
{
    extern __shared__ float s[];
    float* h_s  = s;            // 128*36 = 4608
    float* ejT  = s + 4608;     // 32*132 = 4224
    float* agA  = s + 12928;    // 128*36 = 4608   (ci_s slot unused)
    float* agB  = s + 17536;    // 128*36 = 4608
    float* upd  = s + 22144;    // 128*36 = 4608
    float* Wep  = s + 26752;    // 2048 (packed [c][d][{wj,wi}])
    float* be_s = s + 28800;    // 32
    float* Wa_s = s + 28832;    // 1024
    float* ba_s = s + 29856;    // 32
    float* Wup  = s + 29888;    // 2048 (packed [c][d][{wh,wa}])
    float* bu_s = s + 31936;    // 32
    float* Wd_s = s + 31968;    // 128
    float* bd_s = s + 32096;    // 4
    // total 32100 floats = 128400 B

    const int t = blockIdx.x;
    const int tid = threadIdx.x;
    const int d = tid & 31;
    const int g = tid >> 5;      // 0..31

    {
        int idx = tid * 4;
        int i = idx >> 5, c = idx & 31;
        float4 v = *(const float4*)&g_h[t * 4096 + idx];
        *(float4*)&h_s[i * 36 + c] = v;
    }
    for (int idx = tid; idx < 2048; idx += 1024) {
        float v = We[idx];
        int half = idx >> 10;
        int c = (idx >> 5) & 31;
        int dd = idx & 31;
        Wep[c * 64 + 2 * dd + half] = v;
    }
    for (int idx = tid; idx < 2048; idx += 1024) {
        float v = Wu[idx];
        int half = idx >> 10;
        int c = (idx >> 5) & 31;
        int dd = idx & 31;
        Wup[c * 64 + 2 * dd + half] = v;
    }
    for (int idx = tid; idx < 1024; idx += 1024) Wa_s[idx] = Wa[idx];
    if (tid < 32) { be_s[tid] = be[tid]; ba_s[tid] = ba[tid]; bu_s[tid] = bu[tid]; }
    else if (tid >= 64 && tid < 192) Wd_s[tid - 64] = Wd[tid - 64];
    else if (tid >= 192 && tid < 196) bd_s[tid - 192] = bd[tid - 192];
    __syncthreads();

    // P1: ejT[d][j] (to smem) and aei (= ci, kept in registers).
    float aej[4], aei[4];
    {
        float bev = be_s[d];
        #pragma unroll
        for (int ii = 0; ii < 4; ii++) { aej[ii] = 0.f; aei[ii] = bev; }
        #pragma unroll
        for (int c4 = 0; c4 < 8; c4++) {
            float2 w0 = *(const float2*)&Wep[(4 * c4 + 0) * 64 + 2 * d];
            float2 w1v = *(const float2*)&Wep[(4 * c4 + 1) * 64 + 2 * d];
            float2 w2v = *(const float2*)&Wep[(4 * c4 + 2) * 64 + 2 * d];
            float2 w3v = *(const float2*)&Wep[(4 * c4 + 3) * 64 + 2 * d];
            #pragma unroll
            for (int ii = 0; ii < 4; ii++) {
                float4 hv = *(const float4*)&h_s[(g + 32 * ii) * 36 + 4 * c4];
                aej[ii] += hv.x * w0.x;  aei[ii] += hv.x * w0.y;
                aej[ii] += hv.y * w1v.x; aei[ii] += hv.y * w1v.y;
                aej[ii] += hv.z * w2v.x; aei[ii] += hv.z * w2v.y;
                aej[ii] += hv.w * w3v.x; aei[ii] += hv.w * w3v.y;
            }
        }
        #pragma unroll
        for (int ii = 0; ii < 4; ii++)
            ejT[d * 132 + g + 32 * ii] = aej[ii];
    }
    __syncthreads();

    // P2: agg0[i][d] = 0.5*(S_d + 128*c_i + Sum_j |ej_j + c_i|) - relu(ej_i+c_i)
    //     cc == aei (registers), diag input == aej (registers).
    {
        float acc[4];
        #pragma unroll
        for (int ii = 0; ii < 4; ii++) acc[ii] = 0.f;
        float S = 0.f;
        const float4* row = (const float4*)&ejT[d * 132];
        #pragma unroll 8
        for (int j4 = 0; j4 < 32; j4++) {
            float4 v = row[j4];
            S += (v.x + v.y) + (v.z + v.w);
            #pragma unroll
            for (int ii = 0; ii < 4; ii++) {
                acc[ii] += fabsf(v.x + aei[ii]);
                acc[ii] += fabsf(v.y + aei[ii]);
                acc[ii] += fabsf(v.z + aei[ii]);
                acc[ii] += fabsf(v.w + aei[ii]);
            }
        }
        #pragma unroll
        for (int ii = 0; ii < 4; ii++) {
            int i = g + 32 * ii;
            float diag = fmaxf(aej[ii] + aei[ii], 0.f);
            agA[i * 36 + d] = 0.5f * (S + 128.f * aei[ii] + acc[ii]) - diag;
        }
    }
    __syncthreads();

    // P3: agg = relu(agg0 @ Wa + ba)
    {
        float acc[4];
        float bav = ba_s[d];
        #pragma unroll
        for (int ii = 0; ii < 4; ii++) acc[ii] = bav;
        #pragma unroll
        for (int c4 = 0; c4 < 8; c4++) {
            float wq0 = Wa_s[(4 * c4 + 0) * 32 + d];
            float wq1 = Wa_s[(4 * c4 + 1) * 32 + d];
            float wq2 = Wa_s[(4 * c4 + 2) * 32 + d];
            float wq3 = Wa_s[(4 * c4 + 3) * 32 + d];
            #pragma unroll
            for (int ii = 0; ii < 4; ii++) {
                float4 av = *(const float4*)&agA[(g + 32 * ii) * 36 + 4 * c4];
                acc[ii] += av.x * wq0 + av.y * wq1 + av.z * wq2 + av.w * wq3;
            }
        }
        #pragma unroll
        for (int ii = 0; ii < 4; ii++)
            agB[(g + 32 * ii) * 36 + d] = fmaxf(acc[ii], 0.f);
    }
    __syncthreads();

    // P4: upd = relu(h @ Wu[:H] + agg @ Wu[H:] + bu)
    {
        float acc[4];
        float buv = bu_s[d];
        #pragma unroll
        for (int ii = 0; ii < 4; ii++) acc[ii] = buv;
        #pragma unroll
        for (int c4 = 0; c4 < 8; c4++) {
            float2 w0 = *(const float2*)&Wup[(4 * c4 + 0) * 64 + 2 * d];
            float2 w1v = *(const float2*)&Wup[(4 * c4 + 1) * 64 + 2 * d];
            float2 w2v = *(const float2*)&Wup[(4 * c4 + 2) * 64 + 2 * d];
            float2 w3v = *(const float2*)&Wup[(4 * c4 + 3) * 64 + 2 * d];
            #pragma unroll
            for (int ii = 0; ii < 4; ii++) {
                int r = (g + 32 * ii) * 36 + 4 * c4;
                float4 hv = *(const float4*)&h_s[r];
                float4 av = *(const float4*)&agB[r];
                acc[ii] += hv.x * w0.x  + av.x * w0.y;
                acc[ii] += hv.y * w1v.x + av.y * w1v.y;
                acc[ii] += hv.z * w2v.x + av.z * w2v.y;
                acc[ii] += hv.w * w3v.x + av.w * w3v.y;
            }
        }
        #pragma unroll
        for (int ii = 0; ii < 4; ii++)
            upd[(g + 32 * ii) * 36 + d] = fmaxf(acc[ii], 0.f);
    }
    __syncthreads();

    // P5: dec = upd @ Wd + bd;  out = x[:, 6+t] + dec  (first 512 threads)
    if (tid < 512) {
        int i = tid >> 2, dd = tid & 3;
        float acc = bd_s[dd];
        #pragma unroll
        for (int dc = 0; dc < 32; dc++)
            acc += upd[i * 36 + dc] * Wd_s[dc * 4 + dd];
        out[(i * TP + t) * 4 + dd] = x[(i * 100 + 6 + t) * 4 + dd] + acc;
    }
}

// ---------------------------------------------------------------------------
extern "C" void kernel_launch(void* const* d_in, const int* in_sizes, int n_in,
                              void* d_out, int out_size)
{
    const float* x  = (const float*)d_in[0];
    const float* w1 = (const float*)d_in[1];
    const float* b1 = (const float*)d_in[2];
    const float* w2 = (const float*)d_in[3];
    const float* b2 = (const float*)d_in[4];
    const float* w3 = (const float*)d_in[5];
    const float* b3 = (const float*)d_in[6];
    const float* We = (const float*)d_in[7];
    const float* be = (const float*)d_in[8];
    const float* Wa = (const float*)d_in[9];
    const float* ba = (const float*)d_in[10];
    const float* Wu = (const float*)d_in[11];
    const float* bu = (const float*)d_in[12];
    const float* Wd = (const float*)d_in[13];
    const float* bd = (const float*)d_in[14];
    float* out = (float*)d_out;

    cudaFuncSetAttribute(swarm_kernel,
                         cudaFuncAttributeMaxDynamicSharedMemorySize, 32100 * 4);

    conv_kernel<<<128, 512>>>(x, w1, b1, w2, b2, w3, b3);
    swarm_kernel<<<94, 1024, 32100 * 4>>>(x, We, be, Wa, ba, Wu, bu, Wd, bd, out);
}